// round 2
// baseline (speedup 1.0000x reference)
#include <cuda_runtime.h>
#include <cuda_fp16.h>
#include <cstdint>

#define N_DIM   11008
#define K_DIM   4096
#define KW      2048      // int32 words per weight row (one nibble-pair per word)
#define NCHUNK  32        // K chunks of 128 (== scale group)
#define CW      64        // int32 words per row per chunk
#define APITCH  272       // smem pitch (bytes) for A rows (256B data + pad)
#define XPITCH  272       // smem pitch (bytes) for x tokens (256B fp16 data + pad)
#define ABYTES  (128 * APITCH)          // 34816
#define XBYTES  (32  * XPITCH)          // 8704
#define BUFB    (ABYTES + XBYTES)       // 43520 per buffer, x2 buffers

__device__ __half g_x16[32 * K_DIM];   // fp16 copy of x (values are exactly fp16-representable)

__device__ __forceinline__ void cpa16(uint32_t dst, const void* src) {
    asm volatile("cp.async.cg.shared.global [%0], [%1], 16;" :: "r"(dst), "l"(src));
}
__device__ __forceinline__ uint32_t lds32(uint32_t a) {
    uint32_t v; asm volatile("ld.shared.b32 %0, [%1];" : "=r"(v) : "r"(a)); return v;
}
// low byte of w (two nibbles) -> fp16x2 {lo_nib-8, hi_nib-8}, exact
__device__ __forceinline__ uint32_t cvt_pair(uint32_t w) {
    uint32_t p = ((w | (w << 12)) & 0x000F000Fu) | 0x64006400u;
    uint32_t r;
    asm("sub.f16x2 %0, %1, %2;" : "=r"(r) : "r"(p), "r"(0x64086408u));
    return r;
}
__device__ __forceinline__ void mma16816(float* d,
    uint32_t a0, uint32_t a1, uint32_t a2, uint32_t a3,
    uint32_t b0, uint32_t b1) {
    asm volatile(
        "mma.sync.aligned.m16n8k16.row.col.f32.f16.f16.f32 "
        "{%0,%1,%2,%3}, {%4,%5,%6,%7}, {%8,%9}, {%0,%1,%2,%3};"
        : "+f"(d[0]), "+f"(d[1]), "+f"(d[2]), "+f"(d[3])
        : "r"(a0), "r"(a1), "r"(a2), "r"(a3), "r"(b0), "r"(b1));
}

extern __shared__ char smem_raw[];

__global__ void cvt_x_kernel(const float* __restrict__ x, int n) {
    int i = blockIdx.x * blockDim.x + threadIdx.x;
    int stride = gridDim.x * blockDim.x;
    for (; i < n; i += stride) g_x16[i] = __float2half(x[i]);
}

__device__ __forceinline__ void stage_chunk(uint32_t sb, int buf, int c, int tid, int nb,
                                            const int* __restrict__ wp) {
    uint32_t aB = sb + (uint32_t)buf * BUFB;
    uint32_t xB = aB + ABYTES;
    const int* wsrc = wp + (size_t)nb * KW + c * CW;
    #pragma unroll
    for (int i = 0; i < 8; i++) {
        int idx = tid + i * 256;
        int row = idx >> 4, seg = idx & 15;
        cpa16(aB + row * APITCH + seg * 16, wsrc + (size_t)row * KW + seg * 4);
    }
    const __half* xsrc = g_x16 + c * 128;
    {
        int idx = tid;           // 512 vectors of 16B: 32 tok x 16 segs; 256 thr x 2
        #pragma unroll
        for (int i = 0; i < 2; i++) {
            int tok = idx >> 4, seg = idx & 15;
            cpa16(xB + tok * XPITCH + seg * 16, xsrc + (size_t)tok * K_DIM + seg * 8);
            idx += 256;
        }
    }
}

__global__ void __launch_bounds__(256, 1)
w4a16_mma_kernel(const int* __restrict__ wp,
                 const float* __restrict__ sc,
                 float* __restrict__ out) {
    const int tid  = threadIdx.x;
    const int warp = tid >> 5;
    const int lane = tid & 31;
    const int g = lane >> 2;          // group-of-4 id (0..7)
    const int t = lane & 3;           // thread in group (0..3)
    const int nb = blockIdx.x * 128;  // N base for this CTA

    const uint32_t sb = (uint32_t)__cvta_generic_to_shared(smem_raw);

    float acc[4][4];
    #pragma unroll
    for (int i = 0; i < 4; i++)
        #pragma unroll
        for (int j = 0; j < 4; j++) acc[i][j] = 0.0f;

    stage_chunk(sb, 0, 0, tid, nb, wp);
    asm volatile("cp.async.commit_group;" ::: "memory");

    for (int c = 0; c < NCHUNK; c++) {
        asm volatile("cp.async.wait_group 0;" ::: "memory");
        __syncthreads();
        if (c + 1 < NCHUNK) {
            stage_chunk(sb, (c + 1) & 1, c + 1, tid, nb, wp);
            asm volatile("cp.async.commit_group;" ::: "memory");
        }

        const uint32_t aB = sb + (uint32_t)(c & 1) * BUFB;
        const uint32_t xB = aB + ABYTES;
        // A row base addresses: rows (warp*16+g) and (+8); word 8s+t holds k-pair 16s+2t
        const uint32_t aAddr0 = aB + (warp * 16 + g) * APITCH + t * 4;
        const uint32_t aAddr1 = aAddr0 + 8 * APITCH;

        float dd[4][4];
        #pragma unroll
        for (int i = 0; i < 4; i++)
            #pragma unroll
            for (int j = 0; j < 4; j++) dd[i][j] = 0.0f;

        #pragma unroll
        for (int s = 0; s < 8; s++) {
            uint32_t w00 = lds32(aAddr0 + s * 32);        // word 8s+t   -> k = 16s+2t
            uint32_t w10 = lds32(aAddr1 + s * 32);
            uint32_t w01 = lds32(aAddr0 + s * 32 + 16);   // word 8s+t+4 -> k = 16s+2t+8
            uint32_t w11 = lds32(aAddr1 + s * 32 + 16);
            uint32_t A0 = cvt_pair(w00);   // (row g,   k lo)
            uint32_t A1 = cvt_pair(w10);   // (row g+8, k lo)
            uint32_t A2 = cvt_pair(w01);   // (row g,   k hi)
            uint32_t A3 = cvt_pair(w11);   // (row g+8, k hi)
            #pragma unroll
            for (int q = 0; q < 4; q++) {  // token groups of 8
                uint32_t bbase = xB + (8 * q + g) * XPITCH + s * 32 + t * 4;
                uint32_t b0 = lds32(bbase);        // fp16x2: x[tok][16s+2t .. +1]
                uint32_t b1 = lds32(bbase + 16);   // fp16x2: x[tok][16s+2t+8 .. +1]
                mma16816(dd[q], A0, A1, A2, A3, b0, b1);
            }
        }

        // per-group scales (group index == chunk index), fp32
        float s0 = sc[(size_t)(nb + warp * 16 + g)     * NCHUNK + c];
        float s1 = sc[(size_t)(nb + warp * 16 + g + 8) * NCHUNK + c];
        #pragma unroll
        for (int q = 0; q < 4; q++) {
            acc[q][0] += dd[q][0] * s0;
            acc[q][1] += dd[q][1] * s0;
            acc[q][2] += dd[q][2] * s1;
            acc[q][3] += dd[q][3] * s1;
        }
    }

    // writeback (fp32 out, rounded through fp16 to match reference astype(float16))
    const int n0 = nb + warp * 16 + g;
    #pragma unroll
    for (int q = 0; q < 4; q++) {
        int m0 = 8 * q + 2 * t;
        out[(size_t)m0       * N_DIM + n0    ] = __half2float(__float2half(acc[q][0]));
        out[(size_t)(m0 + 1) * N_DIM + n0    ] = __half2float(__float2half(acc[q][1]));
        out[(size_t)m0       * N_DIM + n0 + 8] = __half2float(__float2half(acc[q][2]));
        out[(size_t)(m0 + 1) * N_DIM + n0 + 8] = __half2float(__float2half(acc[q][3]));
    }
}

extern "C" void kernel_launch(void* const* d_in, const int* in_sizes, int n_in,
                              void* d_out, int out_size) {
    const float* x  = (const float*)d_in[0];
    const int*   wp = (const int*)d_in[1];
    const float* sc = (const float*)d_in[2];
    float*       out = (float*)d_out;

    cvt_x_kernel<<<128, 256>>>(x, 32 * K_DIM);

    cudaFuncSetAttribute(w4a16_mma_kernel,
                         cudaFuncAttributeMaxDynamicSharedMemorySize, 2 * BUFB);
    w4a16_mma_kernel<<<N_DIM / 128, 256, 2 * BUFB>>>(wp, sc, out);
}

// round 3
// speedup vs baseline: 1.0494x; 1.0494x over previous
#include <cuda_runtime.h>
#include <cuda_fp16.h>
#include <cstdint>

#define N_DIM   11008
#define K_DIM   4096
#define KW      2048      // int32 words per weight row (one nibble-pair per word)
#define NCHUNK  32        // K chunks of 128 (== scale group)
#define CW      64        // int32 words per row per chunk
#define APITCH  272       // smem pitch (bytes) for A rows (256B data + pad)
#define XPITCH  272       // smem pitch (bytes) for x tokens (256B fp16 data + pad)
#define ABYTES  (128 * APITCH)          // 34816
#define XBYTES  (32  * XPITCH)          // 8704
#define BUFB    (ABYTES + XBYTES)       // 43520 per stage
#define NSTAGE  4                       // 174080 bytes total dynamic smem

__device__ __half g_x16[32 * K_DIM];   // fp16 copy of x (values exactly fp16-representable)

__device__ __forceinline__ void cpa16(uint32_t dst, const void* src) {
    asm volatile("cp.async.cg.shared.global [%0], [%1], 16;" :: "r"(dst), "l"(src));
}
__device__ __forceinline__ uint32_t lds32(uint32_t a) {
    uint32_t v; asm volatile("ld.shared.b32 %0, [%1];" : "=r"(v) : "r"(a)); return v;
}
// low byte of w (two nibbles) -> fp16x2 {lo_nib-8, hi_nib-8}, exact
__device__ __forceinline__ uint32_t cvt_pair(uint32_t w) {
    uint32_t p = ((w | (w << 12)) & 0x000F000Fu) | 0x64006400u;
    uint32_t r;
    asm("sub.f16x2 %0, %1, %2;" : "=r"(r) : "r"(p), "r"(0x64086408u));
    return r;
}
__device__ __forceinline__ void mma16816(float* d,
    uint32_t a0, uint32_t a1, uint32_t a2, uint32_t a3,
    uint32_t b0, uint32_t b1) {
    asm volatile(
        "mma.sync.aligned.m16n8k16.row.col.f32.f16.f16.f32 "
        "{%0,%1,%2,%3}, {%4,%5,%6,%7}, {%8,%9}, {%0,%1,%2,%3};"
        : "+f"(d[0]), "+f"(d[1]), "+f"(d[2]), "+f"(d[3])
        : "r"(a0), "r"(a1), "r"(a2), "r"(a3), "r"(b0), "r"(b1));
}

extern __shared__ char smem_raw[];

__global__ void cvt_x_kernel(const float* __restrict__ x, int n) {
    int i = blockIdx.x * blockDim.x + threadIdx.x;
    int stride = gridDim.x * blockDim.x;
    for (; i < n; i += stride) g_x16[i] = __float2half(x[i]);
}

__device__ __forceinline__ void stage_chunk(uint32_t sb, int buf, int c, int tid, int nb,
                                            const int* __restrict__ wp) {
    uint32_t aB = sb + (uint32_t)buf * BUFB;
    uint32_t xB = aB + ABYTES;
    const int* wsrc = wp + (size_t)nb * KW + c * CW;
    #pragma unroll
    for (int i = 0; i < 8; i++) {
        int idx = tid + i * 256;
        int row = idx >> 4, seg = idx & 15;
        cpa16(aB + row * APITCH + seg * 16, wsrc + (size_t)row * KW + seg * 4);
    }
    const __half* xsrc = g_x16 + c * 128;
    int idx = tid;           // 512 vectors of 16B: 32 tok x 16 segs
    #pragma unroll
    for (int i = 0; i < 2; i++) {
        int tok = idx >> 4, seg = idx & 15;
        cpa16(xB + tok * XPITCH + seg * 16, xsrc + (size_t)tok * K_DIM + seg * 8);
        idx += 256;
    }
}

__global__ void __launch_bounds__(256, 1)
w4a16_mma_kernel(const int* __restrict__ wp,
                 const float* __restrict__ sc,
                 float* __restrict__ out) {
    const int tid  = threadIdx.x;
    const int warp = tid >> 5;
    const int lane = tid & 31;
    const int g = lane >> 2;          // group-of-4 id (0..7)
    const int t = lane & 3;           // thread in group (0..3)
    const int nb = blockIdx.x * 128;  // N base for this CTA

    const uint32_t sb = (uint32_t)__cvta_generic_to_shared(smem_raw);

    float acc[4][4];
    #pragma unroll
    for (int i = 0; i < 4; i++)
        #pragma unroll
        for (int j = 0; j < 4; j++) acc[i][j] = 0.0f;

    // prologue: keep 3 stages in flight
    #pragma unroll
    for (int p = 0; p < 3; p++) {
        stage_chunk(sb, p, p, tid, nb, wp);
        asm volatile("cp.async.commit_group;" ::: "memory");
    }

    const size_t scRow0 = (size_t)(nb + warp * 16 + g) * NCHUNK;
    const size_t scRow1 = scRow0 + 8 * NCHUNK;

    for (int c = 0; c < NCHUNK; c++) {
        asm volatile("cp.async.wait_group 2;" ::: "memory");
        __syncthreads();

        // stage chunk c+3 into buffer (c+3)&3 (held chunk c-1, fully consumed
        // before the barrier above) — staged BEFORE consumption for overlap
        if (c + 3 < NCHUNK) {
            stage_chunk(sb, (c + 3) & (NSTAGE - 1), c + 3, tid, nb, wp);
        }
        asm volatile("cp.async.commit_group;" ::: "memory");

        // hoist scale loads: latency hides under the MMA loop
        float s0 = sc[scRow0 + c];
        float s1 = sc[scRow1 + c];

        const uint32_t aB = sb + (uint32_t)(c & (NSTAGE - 1)) * BUFB;
        const uint32_t xB = aB + ABYTES;
        const uint32_t aAddr0 = aB + (warp * 16 + g) * APITCH + t * 4;
        const uint32_t aAddr1 = aAddr0 + 8 * APITCH;

        float dd[4][4];
        #pragma unroll
        for (int i = 0; i < 4; i++)
            #pragma unroll
            for (int j = 0; j < 4; j++) dd[i][j] = 0.0f;

        #pragma unroll
        for (int s = 0; s < 8; s++) {
            uint32_t w00 = lds32(aAddr0 + s * 32);        // word 8s+t   -> k = 16s+2t
            uint32_t w10 = lds32(aAddr1 + s * 32);
            uint32_t w01 = lds32(aAddr0 + s * 32 + 16);   // word 8s+t+4 -> k = 16s+2t+8
            uint32_t w11 = lds32(aAddr1 + s * 32 + 16);
            uint32_t A0 = cvt_pair(w00);   // (row g,   k lo)
            uint32_t A1 = cvt_pair(w10);   // (row g+8, k lo)
            uint32_t A2 = cvt_pair(w01);   // (row g,   k hi)
            uint32_t A3 = cvt_pair(w11);   // (row g+8, k hi)
            #pragma unroll
            for (int q = 0; q < 4; q++) {  // token groups of 8
                uint32_t bbase = xB + (8 * q + g) * XPITCH + s * 32 + t * 4;
                uint32_t b0 = lds32(bbase);
                uint32_t b1 = lds32(bbase + 16);
                mma16816(dd[q], A0, A1, A2, A3, b0, b1);
            }
        }

        #pragma unroll
        for (int q = 0; q < 4; q++) {
            acc[q][0] += dd[q][0] * s0;
            acc[q][1] += dd[q][1] * s0;
            acc[q][2] += dd[q][2] * s1;
            acc[q][3] += dd[q][3] * s1;
        }
    }

    // writeback (fp32 out, rounded through fp16 to match reference astype(float16))
    const int n0 = nb + warp * 16 + g;
    #pragma unroll
    for (int q = 0; q < 4; q++) {
        int m0 = 8 * q + 2 * t;
        out[(size_t)m0       * N_DIM + n0    ] = __half2float(__float2half(acc[q][0]));
        out[(size_t)(m0 + 1) * N_DIM + n0    ] = __half2float(__float2half(acc[q][1]));
        out[(size_t)m0       * N_DIM + n0 + 8] = __half2float(__float2half(acc[q][2]));
        out[(size_t)(m0 + 1) * N_DIM + n0 + 8] = __half2float(__float2half(acc[q][3]));
    }
}

extern "C" void kernel_launch(void* const* d_in, const int* in_sizes, int n_in,
                              void* d_out, int out_size) {
    const float* x  = (const float*)d_in[0];
    const int*   wp = (const int*)d_in[1];
    const float* sc = (const float*)d_in[2];
    float*       out = (float*)d_out;

    cvt_x_kernel<<<128, 256>>>(x, 32 * K_DIM);

    cudaFuncSetAttribute(w4a16_mma_kernel,
                         cudaFuncAttributeMaxDynamicSharedMemorySize, NSTAGE * BUFB);
    w4a16_mma_kernel<<<N_DIM / 128, 256, NSTAGE * BUFB>>>(wp, sc, out);
}